// round 16
// baseline (speedup 1.0000x reference)
#include <cuda_runtime.h>
#include <cuda_fp16.h>
#include <cstddef>
#include <cstdint>

#define MM 1536
#define BLOCKS 12
#define WPB 4
#define STRIPS 48            /* BLOCKS * WPB */
#define TEND 1568            /* steps per strip */
#define TALLOC 1600
#define PSS 32               /* steps per superstep */
#define NSUP 49              /* ceil(TEND/PSS) = active supersteps per strip */
#define LAGS 2               /* superstep lag between adjacent strips (64 steps) */
#define KTOT (LAGS * (STRIPS - 1) + NSUP)   /* 143 */
#define WINSZ 128            /* boundary ring slots */

#define L2E  1.4426950408889634f
#define LN2  0.6931471805599453f
#define NEGB (-1.0e8f * L2E)

// Pre-skewed, padded theta: g_th3[((s*TALLOC + t)*3 + q)*128 + lane*4 + j]
__device__ float g_th3[(size_t)STRIPS * TALLOC * 384];

// Cross-block rolling boundary windows + barrier state
__device__ float4 g_win[BLOCKS][WINSZ];
struct __align__(128) PadSlot { unsigned v; unsigned pad[31]; };
__device__ PadSlot  g_arrive[BLOCKS];
__device__ unsigned g_phase;

__global__ void hmm_init_kernel() {
    if (threadIdx.x < BLOCKS) g_arrive[threadIdx.x].v = 0;
    if (threadIdx.x == 0) g_phase = 0;
}

__device__ __forceinline__ unsigned ld_acq_u(const unsigned* p) {
    unsigned v;
    asm volatile("ld.acquire.gpu.global.u32 %0, [%1];" : "=r"(v) : "l"(p) : "memory");
    return v;
}
__device__ __forceinline__ void st_rel_u(unsigned* p, unsigned v) {
    asm volatile("st.release.gpu.global.u32 [%0], %1;" :: "l"(p), "r"(v) : "memory");
}
__device__ __forceinline__ float4 ldv4_g(const float4* p) {
    float4 v;
    asm volatile("ld.volatile.global.v4.f32 {%0,%1,%2,%3}, [%4];"
                 : "=f"(v.x), "=f"(v.y), "=f"(v.z), "=f"(v.w) : "l"(p) : "memory");
    return v;
}

__device__ __forceinline__ float ex2_(float x) {
    float y; asm("ex2.approx.ftz.f32 %0, %1;" : "=f"(y) : "f"(x)); return y;
}
__device__ __forceinline__ float lg2_(float x) {
    float y; asm("lg2.approx.ftz.f32 %0, %1;" : "=f"(y) : "f"(x)); return y;
}
__device__ __forceinline__ float lse3_(float a, float b, float c) {
    float hi = fmaxf(a, b), lo = fminf(a, b);
    float m  = fmaxf(hi, c), s2 = fminf(hi, c);
    return m + lg2_(1.0f + ex2_(lo - m) + ex2_(s2 - m));
}
__device__ __forceinline__ float lse2_(float a, float b) {
    float m = fmaxf(a, b), d = fminf(a, b) - m;
    return m + lg2_(1.0f + ex2_(d));
}
__device__ __forceinline__ float lse3h_(float a, float b, float c) {
    float hi = fmaxf(a, b), lo = fminf(a, b);
    float m  = fmaxf(hi, c), s2 = fminf(hi, c);
    __half2 hd = __floats2half2_rn(lo - m, s2 - m);
    __half2 he = h2exp2(hd);
    float e = __low2float(he) + __high2float(he);
    return m + lg2_(1.0f + e);
}

// ---------------- transpose: theta -> padded skewed layout (unchanged) ------
#define TT 32
#define RG 8
#define NCOL (TT + RG - 1)
#define SROW (NCOL * 9)

__global__ void __launch_bounds__(256)
hmm_transpose_kernel(const float* __restrict__ theta)
{
    __shared__ float s[RG][SROW];
    const int g   = blockIdx.x;
    const int T0  = blockIdx.y * TT;
    const int r0  = blockIdx.z * RG;
    const int tid = threadIdx.x;
    const long NTOT = (long)MM * MM * 9;
    const int C0  = T0 - r0 - (RG - 1);

    #pragma unroll
    for (int row = 0; row < RG; row++) {
        long base = (long)(32 * g + r0 + row) * (MM * 9) + (long)C0 * 9;
        for (int i = tid; i < SROW; i += 256) {
            long idx = base + i;
            idx = idx < 0 ? 0 : (idx >= NTOT ? NTOT - 1 : idx);
            s[row][i] = theta[idx] * L2E;
        }
    }
    __syncthreads();

    float* outb = g_th3 + ((size_t)g * TALLOC + T0) * 384 + r0 * 4;
    #pragma unroll
    for (int k = 0; k < 12; k++) {
        int flat = tid + k * 256;
        int j    = flat & 3;
        int row  = (flat >> 2) & 7;
        int rest = flat >> 5;
        int q    = rest % 3;
        int t_i  = rest / 3;
        int e    = q * 4 + j;
        float v  = 0.0f;
        if (e < 9) v = s[row][(t_i - row + 7) * 9 + e];
        outb[(size_t)t_i * 384 + q * 128 + row * 4 + j] = v;
    }
}

// -------- wavefront DP: static schedule, 32-step supersteps, flat barrier ---
__global__ void __launch_bounds__(128, 1)
hmm_fwd_kernel(float* __restrict__ out)
{
    __shared__ float4 swin[WPB][WINSZ];   // input window of each warp
    const int b   = blockIdx.x;
    const int wid = threadIdx.x >> 5;
    const int r   = threadIdx.x & 31;
    const int tid = threadIdx.x;

    for (int i = tid; i < WPB * WINSZ; i += 128)
        ((float4*)swin)[i] = make_float4(NEGB, NEGB, NEGB, 1.0f);
    __syncthreads();

    const int s  = b * WPB + wid;        // global strip
    const int k0 = LAGS * s;             // first active superstep
    const float4* tb4 = (const float4*)g_th3 + (size_t)s * TALLOC * 96 + r;

    const bool consG = (wid == 0 && b > 0);
    const bool prodS = (r == 31) && (wid < WPB - 1);
    const bool prodG = (r == 31) && (wid == WPB - 1) && (b < BLOCKS - 1);
    float4* sout = &swin[(wid < WPB - 1) ? (wid + 1) : 0][0];
    float4* gout = &g_win[b][0];
    const float4* gin = &g_win[(b > 0) ? (b - 1) : 0][0];
    const float4* sin_ = &swin[wid][0];

    float vM = NEGB, vX = NEGB, vY = NEGB;
    float duM, duX, duY;
    duM = duX = duY = (s == 0 && r == 0) ? 0.0f : NEGB;   // V(0,0)=0

    float4 bq[8];
    #pragma unroll
    for (int q = 0; q < 8; q++) bq[q] = make_float4(NEGB, NEGB, NEGB, 1.0f);

    float4 thA[4][3], thB[4][3];
    auto loadGroup = [&](int tbase, float4 (&dst)[4][3]) {
        #pragma unroll
        for (int q = 0; q < 4; q++) {
            const float4* p = tb4 + (size_t)(tbase + q) * 96;
            dst[q][0] = __ldg(p);
            dst[q][1] = __ldg(p + 32);
            dst[q][2] = __ldg(p + 64);
        }
    };

    auto loadBQ = [&](int c0) {          // DP cols c0..c0+7 from ring slots
        #pragma unroll
        for (int q = 0; q < 8; q++) {
            int sl = (c0 + q) & (WINSZ - 1);
            bq[q] = consG ? ldv4_g(gin + sl) : sin_[sl];
        }
    };

    auto emit = [&](int j, float4 o) {   // producer lane 31 writes DP col j
        if (prodS) sout[j & (WINSZ - 1)] = o;
        if (prodG) gout[j & (WINSZ - 1)] = o;
    };

    auto step = [&](int t, const float4 (&th)[3], float4 bb) {
        float nuM = __shfl_up_sync(0xffffffffu, vM, 1);
        float nuX = __shfl_up_sync(0xffffffffu, vX, 1);
        float nuY = __shfl_up_sync(0xffffffffu, vY, 1);
        if (r == 0) { nuM = bb.x; nuX = bb.y; nuY = bb.z; }
        int col = t - r;
        if ((unsigned)col < (unsigned)MM) {
            float a  = lse3_(duM + th[0].x, duX + th[0].y, duY + th[0].z);
            float b2 = lse3_(nuM + th[0].w, nuX + th[1].x, nuY + th[1].y);
            float c  = lse3_(vM  + th[1].z, vX  + th[1].w, vY  + th[2].x);
            vM = a; vX = b2; vY = c;
            emit(col + 1, make_float4(a, b2, c, 1.0f));
        }
        duM = nuM; duX = nuX; duY = nuY;
    };

    auto pairstep = [&](int t, const float4 (&thE)[3], const float4 (&thO)[3],
                        float4 bbE, float4 bbO) {
        float nuM = __shfl_up_sync(0xffffffffu, vM, 1);
        float nuX = __shfl_up_sync(0xffffffffu, vX, 1);
        float nuY = __shfl_up_sync(0xffffffffu, vY, 1);
        if (r == 0) { nuM = bbE.x; nuX = bbE.y; nuY = bbE.z; }
        float zE = vY + thE[2].x;
        float a1 = lse3h_(duM + thE[0].x, duX + thE[0].y, duY + thE[0].z);
        float b1 = lse3h_(nuM + thE[0].w, nuX + thE[1].x, nuY + thE[1].y);
        float w1 = lse2_(vM + thE[1].z, vX + thE[1].w);
        float c1 = lse2_(w1, zE);
        float nuM2 = __shfl_up_sync(0xffffffffu, a1, 1);
        float nuX2 = __shfl_up_sync(0xffffffffu, b1, 1);
        float nuY2 = __shfl_up_sync(0xffffffffu, c1, 1);
        if (r == 0) { nuM2 = bbO.x; nuX2 = bbO.y; nuY2 = bbO.z; }
        float a2 = lse3h_(nuM + thO[0].x, nuX + thO[0].y, nuY + thO[0].z);
        float b2 = lse3h_(nuM2 + thO[0].w, nuX2 + thO[1].x, nuY2 + thO[1].y);
        float w2 = lse2_(a1 + thO[1].z, b1 + thO[1].w);
        float c2 = lse3_(w2, w1 + thO[2].x, zE + thO[2].x);
        if (prodS | prodG) {
            int j = t - 30;
            emit(j,     make_float4(a1, b1, c1, 1.0f));
            emit(j + 1, make_float4(a2, b2, c2, 1.0f));
        }
        vM = a2; vX = b2; vY = c2;
        duM = nuM2; duX = nuX2; duY = nuY2;
    };

    // ---- superstep loop ----
    for (int k = 0; k < KTOT; k++) {
        const int rel = k - k0;
        if (rel >= 0 && rel < NSUP) {
            const int T = rel * PSS;
            if (rel == 0) { loadGroup(0, thA); loadGroup(4, thB); }

            const bool fast = (T >= 32 && T <= 1504);
            #pragma unroll
            for (int h = 0; h < 2; h++) {
                const int T16 = T + h * 16;
                if (fast) {
                    if (r == 0) loadBQ(T16 + 1);
                    pairstep(T16 + 0,  thA[0], thA[1], bq[0], bq[1]);
                    pairstep(T16 + 2,  thA[2], thA[3], bq[2], bq[3]);
                    loadGroup(T16 + 8, thA);
                    pairstep(T16 + 4,  thB[0], thB[1], bq[4], bq[5]);
                    pairstep(T16 + 6,  thB[2], thB[3], bq[6], bq[7]);
                    loadGroup(T16 + 12, thB);
                    if (r == 0) loadBQ(T16 + 9);
                    pairstep(T16 + 8,  thA[0], thA[1], bq[0], bq[1]);
                    pairstep(T16 + 10, thA[2], thA[3], bq[2], bq[3]);
                    loadGroup(T16 + 16, thA);
                    pairstep(T16 + 12, thB[0], thB[1], bq[4], bq[5]);
                    pairstep(T16 + 14, thB[2], thB[3], bq[6], bq[7]);
                    loadGroup(T16 + 20, thB);
                } else {
                    if (r == 0) loadBQ(T16 + 1);
                    step(T16 + 0, thA[0], bq[0]);
                    step(T16 + 1, thA[1], bq[1]);
                    step(T16 + 2, thA[2], bq[2]);
                    step(T16 + 3, thA[3], bq[3]);
                    loadGroup(T16 + 8, thA);
                    step(T16 + 4, thB[0], bq[4]);
                    step(T16 + 5, thB[1], bq[5]);
                    step(T16 + 6, thB[2], bq[6]);
                    step(T16 + 7, thB[3], bq[7]);
                    loadGroup(T16 + 12, thB);
                    if (r == 0) loadBQ(T16 + 9);
                    step(T16 + 8,  thA[0], bq[0]);
                    step(T16 + 9,  thA[1], bq[1]);
                    step(T16 + 10, thA[2], bq[2]);
                    step(T16 + 11, thA[3], bq[3]);
                    loadGroup(T16 + 16, thA);
                    step(T16 + 12, thB[0], bq[4]);
                    step(T16 + 13, thB[1], bq[5]);
                    step(T16 + 14, thB[2], bq[6]);
                    step(T16 + 15, thB[3], bq[7]);
                    loadGroup(T16 + 20, thB);
                }
            }
        }

        // ---- flat single-round barrier ----
        __syncthreads();
        const unsigned target = (unsigned)(k + 1);
        if (b == 0) {
            if (wid == 0) {
                const bool mine = (r >= 1 && r < BLOCKS);
                const unsigned need = ((1u << BLOCKS) - 2u);  // lanes 1..11
                unsigned m;
                do {
                    unsigned v = mine ? ld_acq_u(&g_arrive[r].v) : target;
                    m = __ballot_sync(0xffffffffu, v >= target);
                } while ((m & need) != need);
                if (r == 0) st_rel_u(&g_phase, target);
            }
        } else {
            if (tid == 0) {
                st_rel_u(&g_arrive[b].v, target);
                unsigned ph;
                do { ph = ld_acq_u(&g_phase); } while (ph < target);
            }
        }
        __syncthreads();
    }

    if (s == STRIPS - 1 && r == 31) {
        out[0] = LN2 * lse3_(vM, vX, vY);
    }
}

extern "C" void kernel_launch(void* const* d_in, const int* in_sizes, int n_in,
                              void* d_out, int out_size)
{
    const float* theta = (const float*)d_in[0];
    float* out = (float*)d_out;

    dim3 tgrid(STRIPS, TALLOC / TT, 32 / RG);
    hmm_transpose_kernel<<<tgrid, 256>>>(theta);
    hmm_init_kernel<<<1, 32>>>();
    hmm_fwd_kernel<<<BLOCKS, WPB * 32>>>(out);
}